// round 1
// baseline (speedup 1.0000x reference)
#include <cuda_runtime.h>
#include <cstdint>

#define N_VERTS 262144
#define N_PAIRS 8388608
#define DHAT2 0.0025f
#define EPSF 1e-12f

// Scratch: current coordinates (rest + displacement), fits in L2 (2 MB).
__device__ float2 g_coords[N_VERTS];

// ---------------------------------------------------------------------------
// Kernel A: coords = rest + Uu.reshape(-1,2); also zero the output scalar.
// ---------------------------------------------------------------------------
__global__ void build_coords_kernel(const float* __restrict__ Uu,
                                    const float* __restrict__ rest,
                                    float* __restrict__ out) {
    int i = blockIdx.x * blockDim.x + threadIdx.x;
    if (i < N_VERTS) {
        // Both arrays are [N,2] float32, contiguous: vectorized float2 loads.
        float2 r = reinterpret_cast<const float2*>(rest)[i];
        float2 u = reinterpret_cast<const float2*>(Uu)[i];
        g_coords[i] = make_float2(r.x + u.x, r.y + u.y);
    }
    if (blockIdx.x == 0 && threadIdx.x == 0) {
        out[0] = 0.0f;  // d_out is poisoned to 0xAA; we must initialize it
    }
}

// ---------------------------------------------------------------------------
// Per-pair barrier term (exact reference math, fp32).
// ---------------------------------------------------------------------------
__device__ __forceinline__ float pair_barrier(int iv, int ie0, int ie1) {
    float2 p = __ldg(&g_coords[iv]);
    float2 a = __ldg(&g_coords[ie0]);
    float2 b = __ldg(&g_coords[ie1]);

    float abx = b.x - a.x, aby = b.y - a.y;
    float apx = p.x - a.x, apy = p.y - a.y;
    float denom = abx * abx + aby * aby;
    float t = (apx * abx + apy * aby) / fmaxf(denom, EPSF);
    t = fminf(fmaxf(t, 0.0f), 1.0f);
    float dx = apx - t * abx;
    float dy = apy - t * aby;
    float d2 = dx * dx + dy * dy;

    if (d2 < DHAT2) {
        float d2s = fmaxf(d2, EPSF);
        float m = d2s - DHAT2;
        return -(m * m) * logf(d2s / DHAT2);
    }
    return 0.0f;
}

// ---------------------------------------------------------------------------
// Kernel B: grid-stride over pairs in int4 groups (coalesced 128-bit index
// loads), gather coords (L2-resident), reduce.
// ---------------------------------------------------------------------------
__global__ void __launch_bounds__(256)
barrier_energy_kernel(const int4* __restrict__ pv4,
                      const int4* __restrict__ pe04,
                      const int4* __restrict__ pe14,
                      float* __restrict__ out) {
    const int n4 = N_PAIRS / 4;
    double acc = 0.0;

    for (int idx = blockIdx.x * blockDim.x + threadIdx.x; idx < n4;
         idx += gridDim.x * blockDim.x) {
        int4 v  = __ldg(&pv4[idx]);
        int4 e0 = __ldg(&pe04[idx]);
        int4 e1 = __ldg(&pe14[idx]);

        float s = pair_barrier(v.x, e0.x, e1.x)
                + pair_barrier(v.y, e0.y, e1.y)
                + pair_barrier(v.z, e0.z, e1.z)
                + pair_barrier(v.w, e0.w, e1.w);
        acc += (double)s;
    }

    // Warp reduction
    #pragma unroll
    for (int off = 16; off > 0; off >>= 1)
        acc += __shfl_xor_sync(0xFFFFFFFFu, acc, off);

    // Block reduction via shared memory
    __shared__ double warp_sums[8];
    int lane = threadIdx.x & 31;
    int wid = threadIdx.x >> 5;
    if (lane == 0) warp_sums[wid] = acc;
    __syncthreads();

    if (wid == 0) {
        double v = (lane < (blockDim.x >> 5)) ? warp_sums[lane] : 0.0;
        #pragma unroll
        for (int off = 4; off > 0; off >>= 1)
            v += __shfl_xor_sync(0xFFFFFFFFu, v, off);
        if (lane == 0)
            atomicAdd(out, (float)v);
    }
}

// ---------------------------------------------------------------------------
extern "C" void kernel_launch(void* const* d_in, const int* in_sizes, int n_in,
                              void* d_out, int out_size) {
    const float* Uu   = (const float*)d_in[0];
    const float* rest = (const float*)d_in[1];
    const int4* pv  = (const int4*)d_in[2];
    const int4* pe0 = (const int4*)d_in[3];
    const int4* pe1 = (const int4*)d_in[4];
    float* out = (float*)d_out;

    build_coords_kernel<<<(N_VERTS + 255) / 256, 256>>>(Uu, rest, out);

    // 148 SMs; aim for ~14 blocks/SM of 256 threads -> good occupancy + MLP.
    barrier_energy_kernel<<<2048, 256>>>(pv, pe0, pe1, out);
}